// round 9
// baseline (speedup 1.0000x reference)
#include <cuda_runtime.h>
#include <cuda_bf16.h>

// GNN_Attention: N=50000, E=800000, IN=8, ED=2, H=2, C=64, HID=64, OUT=2
#define MAXN 50000
#define MAXE 800000
#define HC   128
#define HID  64
#define NEG_SLOPE 0.2f

// -------- static device scratch --------
__device__ __align__(16) float g_xl[MAXN * HC];
__device__ __align__(16) float g_xr[MAXN * HC];
__device__ __align__(16) float g_expl[MAXE * 2];   // (p0,p1) per edge, CSR order
__device__ __align__(16) float g_dinv[MAXN];
__device__ __align__(16) float g_hacc[MAXN * HC];  // h = relu(msg/denom + bias)
__device__ __align__(16) float g_hw[MAXN * HID];   // (h @ gcn_W.T) * dinv[n]

// CSR (sorted by dst)
__device__ int   g_cnt[MAXN + 1];
__device__ int   g_row[MAXN + 1];
__device__ int   g_rowcur[MAXN];
__device__ __align__(16) float4 g_es[MAXE];        // {src(bits), ea0, ea1, eid(bits)}
__device__ float g_es_ew[MAXE];

// -------- 1. node projections + zero CSR counters --------
__global__ void k_proj(const float* __restrict__ x,
                       const float* __restrict__ Wl, const float* __restrict__ bl,
                       const float* __restrict__ Wr, const float* __restrict__ br,
                       int N) {
    int idx = blockIdx.x * blockDim.x + threadIdx.x;
    if (idx >= N * HC) return;
    if (idx < N + 1) g_cnt[idx] = 0;

    int n = idx >> 7, ch = idx & 127;
    const float* xv = x + n * 8;
    float sl = bl[ch], sr = br[ch];
    #pragma unroll
    for (int i = 0; i < 8; i++) {
        float xi = xv[i];
        sl += xi * Wl[ch * 8 + i];
        sr += xi * Wr[ch * 8 + i];
    }
    g_xl[idx] = sl;
    g_xr[idx] = sr;
}

// -------- 2. histogram of dst (2 edges/thread) --------
__global__ void k_hist(const int* __restrict__ ei, int E) {
    int t = blockIdx.x * blockDim.x + threadIdx.x;
    int e0 = t * 2;
    if (e0 >= E) return;
    int d0 = ei[E + e0];
    int d1 = (e0 + 1 < E) ? ei[E + e0 + 1] : -1;
    atomicAdd(&g_cnt[d0], 1);
    if (d1 >= 0) atomicAdd(&g_cnt[d1], 1);
}

// -------- 3. exclusive scan -> row offsets (single block) --------
__global__ void k_scan(int N) {
    __shared__ int wsum[32];
    int t = threadIdx.x;              // 1024
    int nb = blockDim.x;
    int CH = (N + nb - 1) / nb;
    int lo = t * CH, hi = min(lo + CH, N);
    int s = 0;
    for (int i = lo; i < hi; i++) s += g_cnt[i];
    int lane = t & 31, wid = t >> 5;
    int v = s;
    #pragma unroll
    for (int o = 1; o < 32; o <<= 1) {
        int u = __shfl_up_sync(0xffffffffu, v, o);
        if (lane >= o) v += u;
    }
    if (lane == 31) wsum[wid] = v;
    __syncthreads();
    if (wid == 0) {
        int xv = wsum[lane];
        #pragma unroll
        for (int o = 1; o < 32; o <<= 1) {
            int u = __shfl_up_sync(0xffffffffu, xv, o);
            if (lane >= o) xv += u;
        }
        wsum[lane] = xv;
    }
    __syncthreads();
    int excl = v - s + (wid > 0 ? wsum[wid - 1] : 0);
    int run = excl;
    for (int i = lo; i < hi; i++) {
        g_row[i] = run;
        g_rowcur[i] = run;
        run += g_cnt[i];
    }
    if (hi == N) g_row[N] = run;
}

// -------- 4. scatter edges into packed CSR records (2 edges/thread) --------
__global__ void k_scatter(const int* __restrict__ ei,
                          const float* __restrict__ ea, int E) {
    int t = blockIdx.x * blockDim.x + threadIdx.x;
    int e0 = t * 2;
    if (e0 >= E) return;
    int e1 = min(e0 + 1, E - 1);
    int s0 = ei[e0],      s1 = ei[e1];
    int d0 = ei[E + e0],  d1 = ei[E + e1];
    float2 a0 = ((const float2*)ea)[e0];
    float2 a1 = ((const float2*)ea)[e1];
    int p0 = atomicAdd(&g_rowcur[d0], 1);
    g_es[p0] = make_float4(__int_as_float(s0), a0.x, a0.y, __int_as_float(e0));
    if (e0 + 1 < E) {
        int p1 = atomicAdd(&g_rowcur[d1], 1);
        g_es[p1] = make_float4(__int_as_float(s1), a1.x, a1.y, __int_as_float(e1));
    }
}

// -------- 5. GAT mainloop: warp/node, 2-stage pipeline x 2 edges ----------
__global__ void __launch_bounds__(256) k_gat(const float* __restrict__ We,
                      const float* __restrict__ att,
                      const float* __restrict__ gat_bias,
                      float* __restrict__ alpha_out, int N) {
    int w    = (blockIdx.x * blockDim.x + threadIdx.x) >> 5;
    int lane = threadIdx.x & 31;
    if (w >= N) return;
    int n = w;
    int r0 = g_row[n], r1 = g_row[n + 1];

    float4 at   = ((const float4*)att)[lane];
    float4 we01 = ((const float4*)We)[2 * lane];
    float4 we23 = ((const float4*)We)[2 * lane + 1];
    float4 xrv  = ((const float4*)g_xr)[n * 32 + lane];

    float4 macc = make_float4(0.f, 0.f, 0.f, 0.f);
    float dsum = 0.f;

    float4 pk0 = make_float4(0.f, 0.f, 0.f, 0.f), pk1 = pk0;
    float4 a0  = make_float4(0.f, 0.f, 0.f, 0.f), a1  = a0;

    // prologue: stage group at r0 (clamped second edge)
    if (r0 < r1) {
        pk0 = g_es[r0];
        a0  = ((const float4*)g_xl)[__float_as_int(pk0.x) * 32 + lane];
        int ic = min(r0 + 1, r1 - 1);
        pk1 = g_es[ic];
        a1  = ((const float4*)g_xl)[__float_as_int(pk1.x) * 32 + lane];
    }
    for (int i = r0; i < r1; i += 2) {
        float4 cpk0 = pk0, cpk1 = pk1, ca0 = a0, ca1 = a1;
        // prefetch next group while computing this one
        if (i + 2 < r1) {
            pk0 = g_es[i + 2];
            a0  = ((const float4*)g_xl)[__float_as_int(pk0.x) * 32 + lane];
            int ic = min(i + 3, r1 - 1);
            pk1 = g_es[ic];
            a1  = ((const float4*)g_xl)[__float_as_int(pk1.x) * 32 + lane];
        }
        // logits for both edges (interleaved)
        float e00 = we01.x * cpk0.y + we01.y * cpk0.z;
        float e01 = we01.z * cpk0.y + we01.w * cpk0.z;
        float e02 = we23.x * cpk0.y + we23.y * cpk0.z;
        float e03 = we23.z * cpk0.y + we23.w * cpk0.z;
        float e10 = we01.x * cpk1.y + we01.y * cpk1.z;
        float e11 = we01.z * cpk1.y + we01.w * cpk1.z;
        float e12 = we23.x * cpk1.y + we23.y * cpk1.z;
        float e13 = we23.z * cpk1.y + we23.w * cpk1.z;
        float z, s0 = 0.f, s1 = 0.f;
        z = ca0.x + xrv.x + e00; z = z > 0.f ? z : NEG_SLOPE * z; s0 += z * at.x;
        z = ca0.y + xrv.y + e01; z = z > 0.f ? z : NEG_SLOPE * z; s0 += z * at.y;
        z = ca0.z + xrv.z + e02; z = z > 0.f ? z : NEG_SLOPE * z; s0 += z * at.z;
        z = ca0.w + xrv.w + e03; z = z > 0.f ? z : NEG_SLOPE * z; s0 += z * at.w;
        z = ca1.x + xrv.x + e10; z = z > 0.f ? z : NEG_SLOPE * z; s1 += z * at.x;
        z = ca1.y + xrv.y + e11; z = z > 0.f ? z : NEG_SLOPE * z; s1 += z * at.y;
        z = ca1.z + xrv.z + e12; z = z > 0.f ? z : NEG_SLOPE * z; s1 += z * at.z;
        z = ca1.w + xrv.w + e13; z = z > 0.f ? z : NEG_SLOPE * z; s1 += z * at.w;
        #pragma unroll
        for (int o = 8; o >= 1; o >>= 1) {
            s0 += __shfl_xor_sync(0xffffffffu, s0, o, 16);
            s1 += __shfl_xor_sync(0xffffffffu, s1, o, 16);
        }
        float p0 = __expf(s0);   // |logit| small: max-subtraction not needed
        float p1 = __expf(s1);
        // lanes 0 / 16 hold head0 / head1 sums respectively
        if (lane == 0)  g_expl[2 * i] = p0;
        if (lane == 16) g_expl[2 * i + 1] = p0;
        macc.x += p0 * ca0.x; macc.y += p0 * ca0.y;
        macc.z += p0 * ca0.z; macc.w += p0 * ca0.w;
        dsum += p0;
        if (i + 1 < r1) {
            if (lane == 0)  g_expl[2 * i + 2] = p1;
            if (lane == 16) g_expl[2 * i + 3] = p1;
            macc.x += p1 * ca1.x; macc.y += p1 * ca1.y;
            macc.z += p1 * ca1.z; macc.w += p1 * ca1.w;
            dsum += p1;
        }
    }

    // dsum on lanes 0-15 = denom(head0); lanes 16-31 = denom(head1)
    float inv = dsum > 0.f ? __fdividef(1.f, dsum) : 0.f;
    float4 b4 = ((const float4*)gat_bias)[lane];
    float4 h;
    h.x = fmaxf(macc.x * inv + b4.x, 0.f);
    h.y = fmaxf(macc.y * inv + b4.y, 0.f);
    h.z = fmaxf(macc.z * inv + b4.z, 0.f);
    h.w = fmaxf(macc.w * inv + b4.w, 0.f);
    ((float4*)g_hacc)[n * 32 + lane] = h;

    // alpha / ew / deg (lane-parallel over the row)
    __syncwarp();
    __threadfence_block();
    float inv0 = __shfl_sync(0xffffffffu, inv, 0);
    float inv1 = __shfl_sync(0xffffffffu, inv, 16);
    float degs = 0.f;
    for (int q = r0 + lane; q < r1; q += 32) {
        float2 pe = ((const float2*)g_expl)[q];
        int eid = __float_as_int(g_es[q].w);
        float av0 = pe.x * inv0, av1 = pe.y * inv1;
        ((float2*)alpha_out)[eid] = make_float2(av0, av1);
        float ew = 0.5f * (av0 + av1);
        g_es_ew[q] = ew;
        degs += ew;
    }
    #pragma unroll
    for (int o = 16; o >= 1; o >>= 1)
        degs += __shfl_xor_sync(0xffffffffu, degs, o);
    if (lane == 0) g_dinv[n] = degs > 0.f ? rsqrtf(degs) : 0.f;
}

// -------- 6. tiled GEMM: g_hw = (h @ gcn_W.T) * dinv[n] --------
#define NHB 64
#define WP  68
__global__ void k_node_hw(const float* __restrict__ gcn_W, int N) {
    __shared__ __align__(16) float Wsh[64 * WP];
    __shared__ __align__(16) float hsh[64 * WP];
    int t = threadIdx.x;                 // 256
    int base = blockIdx.x * NHB;

    int tx = t & 15;
    int ty = t >> 4;
    float acc[4][4];
    #pragma unroll
    for (int i = 0; i < 4; i++)
        #pragma unroll
        for (int j = 0; j < 4; j++) acc[i][j] = 0.f;

    #pragma unroll
    for (int ph = 0; ph < 2; ph++) {
        {
            int k = t & 63, cb = t >> 6;
            #pragma unroll
            for (int j = 0; j < 16; j++) {
                int c = cb + j * 4;
                Wsh[k * WP + c] = gcn_W[c * HC + ph * 64 + k];
            }
        }
        {
            int c = t & 63, nb = t >> 6;
            #pragma unroll
            for (int j = 0; j < 16; j++) {
                int nl = nb + j * 4;
                int n = base + nl;
                hsh[c * WP + nl] = (n < N) ? g_hacc[n * HC + ph * 64 + c] : 0.f;
            }
        }
        __syncthreads();
        #pragma unroll 4
        for (int k = 0; k < 64; k++) {
            float4 wv = *(const float4*)&Wsh[k * WP + tx * 4];
            float4 hv = *(const float4*)&hsh[k * WP + ty * 4];
            acc[0][0] += hv.x * wv.x; acc[0][1] += hv.x * wv.y;
            acc[0][2] += hv.x * wv.z; acc[0][3] += hv.x * wv.w;
            acc[1][0] += hv.y * wv.x; acc[1][1] += hv.y * wv.y;
            acc[1][2] += hv.y * wv.z; acc[1][3] += hv.y * wv.w;
            acc[2][0] += hv.z * wv.x; acc[2][1] += hv.z * wv.y;
            acc[2][2] += hv.z * wv.z; acc[2][3] += hv.z * wv.w;
            acc[3][0] += hv.w * wv.x; acc[3][1] += hv.w * wv.y;
            acc[3][2] += hv.w * wv.z; acc[3][3] += hv.w * wv.w;
        }
        __syncthreads();
    }
    #pragma unroll
    for (int i = 0; i < 4; i++) {
        int n = base + ty * 4 + i;
        if (n < N) {
            float di = g_dinv[n];
            ((float4*)g_hw)[n * 16 + tx] =
                make_float4(acc[i][0] * di, acc[i][1] * di,
                            acc[i][2] * di, acc[i][3] * di);
        }
    }
}

// -------- 7. GCN aggregate + output head: warp/node, 2-stage pipeline ------
__global__ void __launch_bounds__(256) k_gcn_out(const float* __restrict__ gcn_b,
                          const float* __restrict__ out_W,
                          const float* __restrict__ out_b,
                          float* __restrict__ out, int N) {
    int w    = (blockIdx.x * blockDim.x + threadIdx.x) >> 5;
    int lane = threadIdx.x & 31;
    if (w >= N) return;
    int n = w;
    int r0 = g_row[n], r1 = g_row[n + 1];
    float dinvn = g_dinv[n];

    float2 acc = make_float2(0.f, 0.f);
    int   s0 = 0, s1 = 0;
    float w0 = 0.f, w1 = 0.f;
    float2 h0 = make_float2(0.f, 0.f), h1 = h0;

    if (r0 < r1) {
        s0 = __float_as_int(g_es[r0].x);
        w0 = g_es_ew[r0];
        h0 = ((const float2*)g_hw)[s0 * 32 + lane];
        int ic = min(r0 + 1, r1 - 1);
        s1 = __float_as_int(g_es[ic].x);
        w1 = g_es_ew[ic];
        h1 = ((const float2*)g_hw)[s1 * 32 + lane];
    }
    for (int i = r0; i < r1; i += 2) {
        float cw0 = w0, cw1 = w1;
        float2 ch0 = h0, ch1 = h1;
        if (i + 2 < r1) {
            s0 = __float_as_int(g_es[i + 2].x);
            w0 = g_es_ew[i + 2];
            h0 = ((const float2*)g_hw)[s0 * 32 + lane];
            int ic = min(i + 3, r1 - 1);
            s1 = __float_as_int(g_es[ic].x);
            w1 = g_es_ew[ic];
            h1 = ((const float2*)g_hw)[s1 * 32 + lane];
        }
        acc.x += cw0 * ch0.x;
        acc.y += cw0 * ch0.y;
        if (i + 1 < r1) {
            acc.x += cw1 * ch1.x;
            acc.y += cw1 * ch1.y;
        }
    }
    acc.x *= dinvn;
    acc.y *= dinvn;

    float q0 = fmaxf(acc.x + gcn_b[2 * lane],     0.f);
    float q1 = fmaxf(acc.y + gcn_b[2 * lane + 1], 0.f);
    float o0 = q0 * out_W[2 * lane]      + q1 * out_W[2 * lane + 1];
    float o1 = q0 * out_W[64 + 2 * lane] + q1 * out_W[64 + 2 * lane + 1];
    #pragma unroll
    for (int o = 16; o >= 1; o >>= 1) {
        o0 += __shfl_down_sync(0xffffffffu, o0, o);
        o1 += __shfl_down_sync(0xffffffffu, o1, o);
    }
    if (lane == 0) {
        out[2 * n]     = o0 + out_b[0];
        out[2 * n + 1] = o1 + out_b[1];
    }
}

extern "C" void kernel_launch(void* const* d_in, const int* in_sizes, int n_in,
                              void* d_out, int out_size) {
    const float* x        = (const float*)d_in[0];
    const float* ea       = (const float*)d_in[1];
    const int*   ei       = (const int*)d_in[2];   // int32 (JAX x64 disabled)
    const float* Wl       = (const float*)d_in[3];
    const float* bl       = (const float*)d_in[4];
    const float* Wr       = (const float*)d_in[5];
    const float* br       = (const float*)d_in[6];
    const float* We       = (const float*)d_in[7];
    const float* att      = (const float*)d_in[8];
    const float* gat_bias = (const float*)d_in[9];
    const float* gcn_W    = (const float*)d_in[10];
    const float* gcn_b    = (const float*)d_in[11];
    const float* out_W    = (const float*)d_in[12];
    const float* out_b    = (const float*)d_in[13];

    int N = in_sizes[0] / 8;     // IN=8
    int E = in_sizes[1] / 2;     // ED=2

    float* out       = (float*)d_out;
    float* alpha_out = (float*)d_out + (size_t)N * 2;

    const int NT = 256;
    k_proj<<<(N * HC + NT - 1) / NT, NT>>>(x, Wl, bl, Wr, br, N);
    k_hist<<<(E / 2 + NT - 1) / NT, NT>>>(ei, E);
    k_scan<<<1, 1024>>>(N);
    k_scatter<<<(E / 2 + NT - 1) / NT, NT>>>(ei, ea, E);
    k_gat<<<(int)(((size_t)N * 32 + NT - 1) / NT), NT>>>(We, att, gat_bias, alpha_out, N);
    k_node_hw<<<(N + NHB - 1) / NHB, 256>>>(gcn_W, N);
    k_gcn_out<<<(int)(((size_t)N * 32 + NT - 1) / NT), NT>>>(gcn_b, out_W, out_b, out, N);
}

// round 10
// speedup vs baseline: 1.2341x; 1.2341x over previous
#include <cuda_runtime.h>
#include <cuda_bf16.h>

// GNN_Attention: N=50000, E=800000, IN=8, ED=2, H=2, C=64, HID=64, OUT=2
#define MAXN 50000
#define MAXE 800000
#define HC   128
#define HID  64
#define NEG_SLOPE 0.2f

// -------- static device scratch (16B aligned for float4 / red.v4) --------
__device__ __align__(16) float g_xl[MAXN * HC];
__device__ __align__(16) float g_xr[MAXN * HC];
__device__ __align__(16) float g_expl[MAXE * 2];
__device__ __align__(16) float g_ew[MAXE];
__device__ __align__(16) float g_denom[MAXN * 2];
__device__ __align__(16) float g_deg[MAXN];
__device__ __align__(16) float g_dinv[MAXN];
__device__ __align__(16) float g_hacc[MAXN * HC];   // Σ p·xl[src]  (unnormalized)
__device__ __align__(16) float g_hw[MAXN * HID];    // (h @ gcn_W.T) * dinv[n]
__device__ __align__(16) float g_h2acc[MAXN * HID];

__device__ __forceinline__ void red_add_v4(float* p, float4 v) {
    asm volatile("red.global.add.v4.f32 [%0], {%1,%2,%3,%4};"
                 :: "l"(p), "f"(v.x), "f"(v.y), "f"(v.z), "f"(v.w)
                 : "memory");
}
__device__ __forceinline__ void red_add_v2(float* p, float a, float b) {
    asm volatile("red.global.add.v2.f32 [%0], {%1,%2};"
                 :: "l"(p), "f"(a), "f"(b)
                 : "memory");
}

// -------- 1. node projections + zero all accumulators (fused) --------
__global__ void k_proj(const float* __restrict__ x,
                       const float* __restrict__ Wl, const float* __restrict__ bl,
                       const float* __restrict__ Wr, const float* __restrict__ br,
                       int N) {
    int idx = blockIdx.x * blockDim.x + threadIdx.x;
    if (idx >= N * HC) return;
    g_hacc[idx] = 0.f;
    if (idx < N * HID) g_h2acc[idx] = 0.f;
    if (idx < N * 2)   g_denom[idx] = 0.f;
    if (idx < N)       g_deg[idx]   = 0.f;

    int n = idx >> 7, ch = idx & 127;
    const float* xv = x + n * 8;
    float sl = bl[ch], sr = br[ch];
    #pragma unroll
    for (int i = 0; i < 8; i++) {
        float xi = xv[i];
        sl += xi * Wl[ch * 8 + i];
        sr += xi * Wr[ch * 8 + i];
    }
    g_xl[idx] = sl;
    g_xr[idx] = sr;
}

// -------- 2. fused logits + exp + denom + unnormalized message scatter ------
__global__ void k_logits(const int* __restrict__ ei,
                         const float* __restrict__ ea,
                         const float* __restrict__ We,
                         const float* __restrict__ att, int E) {
    int warp = (blockIdx.x * blockDim.x + threadIdx.x) >> 5;
    int lane = threadIdx.x & 31;
    int e0 = warp * 4;
    if (e0 >= E) return;

    float4 at   = ((const float4*)att)[lane];
    float4 we01 = ((const float4*)We)[2 * lane];
    float4 we23 = ((const float4*)We)[2 * lane + 1];

    int src[4], dst[4];
    float2 eav[4];
    #pragma unroll
    for (int j = 0; j < 4; j++) {
        int e = min(e0 + j, E - 1);
        src[j] = ei[e];
        dst[j] = ei[E + e];
        eav[j] = ((const float2*)ea)[e];
    }
    float4 a[4], b[4];
    #pragma unroll
    for (int j = 0; j < 4; j++) a[j] = ((const float4*)g_xl)[src[j] * 32 + lane];
    #pragma unroll
    for (int j = 0; j < 4; j++) b[j] = ((const float4*)g_xr)[dst[j] * 32 + lane];

    float s[4];
    #pragma unroll
    for (int j = 0; j < 4; j++) {
        float e_0 = we01.x * eav[j].x + we01.y * eav[j].y;
        float e_1 = we01.z * eav[j].x + we01.w * eav[j].y;
        float e_2 = we23.x * eav[j].x + we23.y * eav[j].y;
        float e_3 = we23.z * eav[j].x + we23.w * eav[j].y;
        float z, acc = 0.f;
        z = a[j].x + b[j].x + e_0; z = z > 0.f ? z : NEG_SLOPE * z; acc += z * at.x;
        z = a[j].y + b[j].y + e_1; z = z > 0.f ? z : NEG_SLOPE * z; acc += z * at.y;
        z = a[j].z + b[j].z + e_2; z = z > 0.f ? z : NEG_SLOPE * z; acc += z * at.z;
        z = a[j].w + b[j].w + e_3; z = z > 0.f ? z : NEG_SLOPE * z; acc += z * at.w;
        s[j] = acc;
    }
    #pragma unroll
    for (int o = 8; o >= 1; o >>= 1) {
        #pragma unroll
        for (int j = 0; j < 4; j++)
            s[j] += __shfl_xor_sync(0xffffffffu, s[j], o, 16);
    }
    float p[4], pd[4];
    #pragma unroll
    for (int j = 0; j < 4; j++) p[j] = __expf(s[j]);  // |logit| small: no max-sub
    #pragma unroll
    for (int j = 0; j < 4; j++) pd[j] = __shfl_down_sync(0xffffffffu, p[j], 16);

    if (lane == 0) {
        #pragma unroll
        for (int j = 0; j < 4; j++) {
            int e = e0 + j;
            if (e < E) {
                ((float2*)g_expl)[e] = make_float2(p[j], pd[j]);
                red_add_v2(&g_denom[2 * dst[j]], p[j], pd[j]);
            }
        }
    }
    #pragma unroll
    for (int j = 0; j < 4; j++) {
        if (e0 + j < E) {
            float4 m = a[j];
            m.x *= p[j]; m.y *= p[j]; m.z *= p[j]; m.w *= p[j];
            red_add_v4(&g_hacc[dst[j] * HC + lane * 4], m);
        }
    }
}

// -------- 3. light alpha pass: alpha, ew, deg --------
__global__ void k_alpha(const int* __restrict__ ei,
                        float* __restrict__ alpha_out, int E) {
    int t = blockIdx.x * blockDim.x + threadIdx.x;
    int e0 = t * 2;
    if (e0 >= E) return;
    int e1 = min(e0 + 1, E - 1);
    int dst0 = ei[E + e0], dst1 = ei[E + e1];
    float2 p0 = ((const float2*)g_expl)[e0];
    float2 p1 = ((const float2*)g_expl)[e1];
    float2 d0 = ((const float2*)g_denom)[dst0];
    float2 d1 = ((const float2*)g_denom)[dst1];
    float a00 = __fdividef(p0.x, d0.x), a01 = __fdividef(p0.y, d0.y);
    float a10 = __fdividef(p1.x, d1.x), a11 = __fdividef(p1.y, d1.y);
    ((float2*)alpha_out)[e0] = make_float2(a00, a01);
    float ew0 = 0.5f * (a00 + a01);
    g_ew[e0] = ew0;
    atomicAdd(&g_deg[dst0], ew0);
    if (e0 + 1 < E) {
        ((float2*)alpha_out)[e1] = make_float2(a10, a11);
        float ew1 = 0.5f * (a10 + a11);
        g_ew[e1] = ew1;
        atomicAdd(&g_deg[dst1], ew1);
    }
}

// -------- 4. register-tiled node GEMM: 64 nodes/block, 4x4 tile/thread ------
// g_hw = (relu(hacc/denom + bias) @ gcn_W.T) * dinv[n]   (src-side norm folded)
#define NHB 64
#define WP  68
__global__ void k_node_hw(const float* __restrict__ gat_bias,
                          const float* __restrict__ gcn_W, int N) {
    __shared__ __align__(16) float Wsh[64 * WP];   // 17.4 KB
    __shared__ __align__(16) float hsh[64 * WP];   // 17.4 KB
    __shared__ float inv0[NHB], inv1[NHB], dsh[NHB];
    __shared__ float bsh[HC];
    int t = threadIdx.x;                 // 256
    int base = blockIdx.x * NHB;

    if (t < HC) bsh[t] = gat_bias[t];
    if (t < NHB) {
        int n = base + t;
        if (n < N) {
            float2 dn = ((const float2*)g_denom)[n];
            inv0[t] = dn.x > 0.f ? __fdividef(1.f, dn.x) : 0.f;
            inv1[t] = dn.y > 0.f ? __fdividef(1.f, dn.y) : 0.f;
            float dg = g_deg[n];
            float dv = dg > 0.f ? rsqrtf(dg) : 0.f;
            g_dinv[n] = dv;
            dsh[t] = dv;
        } else { inv0[t] = 0.f; inv1[t] = 0.f; dsh[t] = 0.f; }
    }
    __syncthreads();

    int tx = t & 15;          // col group: cols 4tx..4tx+3
    int ty = t >> 4;          // node group: nodes 4ty..4ty+3
    float acc[4][4];
    #pragma unroll
    for (int i = 0; i < 4; i++)
        #pragma unroll
        for (int j = 0; j < 4; j++) acc[i][j] = 0.f;

    #pragma unroll
    for (int ph = 0; ph < 2; ph++) {
        {
            int k = t & 63, cb = t >> 6;
            #pragma unroll
            for (int j = 0; j < 16; j++) {
                int c = cb + j * 4;
                Wsh[k * WP + c] = gcn_W[c * HC + ph * 64 + k];
            }
        }
        {
            int c = t & 63, nb = t >> 6;
            #pragma unroll
            for (int j = 0; j < 16; j++) {
                int nl = nb + j * 4;
                int n = base + nl;
                float v = 0.f;
                if (n < N) {
                    float iv = ph ? inv1[nl] : inv0[nl];
                    v = fmaxf(g_hacc[n * HC + ph * 64 + c] * iv + bsh[ph * 64 + c], 0.f);
                }
                hsh[c * WP + nl] = v;
            }
        }
        __syncthreads();
        #pragma unroll 4
        for (int k = 0; k < 64; k++) {
            float4 w = *(const float4*)&Wsh[k * WP + tx * 4];
            float4 h = *(const float4*)&hsh[k * WP + ty * 4];
            acc[0][0] += h.x * w.x; acc[0][1] += h.x * w.y;
            acc[0][2] += h.x * w.z; acc[0][3] += h.x * w.w;
            acc[1][0] += h.y * w.x; acc[1][1] += h.y * w.y;
            acc[1][2] += h.y * w.z; acc[1][3] += h.y * w.w;
            acc[2][0] += h.z * w.x; acc[2][1] += h.z * w.y;
            acc[2][2] += h.z * w.z; acc[2][3] += h.z * w.w;
            acc[3][0] += h.w * w.x; acc[3][1] += h.w * w.y;
            acc[3][2] += h.w * w.z; acc[3][3] += h.w * w.w;
        }
        __syncthreads();
    }
    #pragma unroll
    for (int i = 0; i < 4; i++) {
        int nl = ty * 4 + i;
        int n = base + nl;
        if (n < N) {
            float di = dsh[nl];         // fold dinv[src] into hw
            float4 o = make_float4(acc[i][0] * di, acc[i][1] * di,
                                   acc[i][2] * di, acc[i][3] * di);
            ((float4*)g_hw)[n * 16 + tx] = o;
        }
    }
}

// -------- 5. GCN edge scatter: h2acc[dst] += ew·hw_scaled[src] --------
// (dinv[src] pre-folded into hw; dinv[dst] applied in k_node_out)
__global__ void k_gcn_edge(const int* __restrict__ ei, int E) {
    int warp = (blockIdx.x * blockDim.x + threadIdx.x) >> 5;
    int lane = threadIdx.x & 31;
    int half = lane >> 4;
    int l    = lane & 15;
    int e0 = warp * 8 + half;
    if (e0 >= E) return;

    int src[4], dst[4];
    float nv[4];
    #pragma unroll
    for (int j = 0; j < 4; j++) {
        int e = min(e0 + 2 * j, E - 1);
        src[j] = ei[e];
        dst[j] = ei[E + e];
        nv[j]  = g_ew[e];
    }
    float4 v[4];
    #pragma unroll
    for (int j = 0; j < 4; j++)
        v[j] = ((const float4*)g_hw)[src[j] * 16 + l];
    #pragma unroll
    for (int j = 0; j < 4; j++) {
        if (e0 + 2 * j < E) {
            float4 m = v[j];
            m.x *= nv[j]; m.y *= nv[j]; m.z *= nv[j]; m.w *= nv[j];
            red_add_v4(&g_h2acc[dst[j] * HID + l * 4], m);
        }
    }
}

// -------- 6. per-node output (applies dinv[dst]) --------
__global__ void k_node_out(const float* __restrict__ gcn_b,
                           const float* __restrict__ out_W,
                           const float* __restrict__ out_b,
                           float* __restrict__ out, int N) {
    int t = blockIdx.x * blockDim.x + threadIdx.x;
    int n = t >> 5;
    if (n >= N) return;
    int lane = t & 31;
    float dv = g_dinv[n];                 // broadcast load per warp
    float2 hv = ((const float2*)g_h2acc)[n * 32 + lane];
    float h0 = fmaxf(hv.x * dv + gcn_b[2 * lane],     0.f);
    float h1 = fmaxf(hv.y * dv + gcn_b[2 * lane + 1], 0.f);
    float s0 = h0 * out_W[2 * lane]      + h1 * out_W[2 * lane + 1];
    float s1 = h0 * out_W[64 + 2 * lane] + h1 * out_W[64 + 2 * lane + 1];
    #pragma unroll
    for (int o = 16; o >= 1; o >>= 1) {
        s0 += __shfl_down_sync(0xffffffffu, s0, o);
        s1 += __shfl_down_sync(0xffffffffu, s1, o);
    }
    if (lane == 0) {
        out[2 * n]     = s0 + out_b[0];
        out[2 * n + 1] = s1 + out_b[1];
    }
}

extern "C" void kernel_launch(void* const* d_in, const int* in_sizes, int n_in,
                              void* d_out, int out_size) {
    const float* x        = (const float*)d_in[0];
    const float* ea       = (const float*)d_in[1];
    const int*   ei       = (const int*)d_in[2];   // int32 (JAX x64 disabled)
    const float* Wl       = (const float*)d_in[3];
    const float* bl       = (const float*)d_in[4];
    const float* Wr       = (const float*)d_in[5];
    const float* br       = (const float*)d_in[6];
    const float* We       = (const float*)d_in[7];
    const float* att      = (const float*)d_in[8];
    const float* gat_bias = (const float*)d_in[9];
    const float* gcn_W    = (const float*)d_in[10];
    const float* gcn_b    = (const float*)d_in[11];
    const float* out_W    = (const float*)d_in[12];
    const float* out_b    = (const float*)d_in[13];

    int N = in_sizes[0] / 8;     // IN=8
    int E = in_sizes[1] / 2;     // ED=2

    float* out       = (float*)d_out;
    float* alpha_out = (float*)d_out + (size_t)N * 2;

    const int NT = 256;
    int warpsL = (E + 3) / 4;   // 4 edges/warp
    int warpsG = (E + 7) / 8;   // 8 edges/warp
    k_proj<<<(N * HC + NT - 1) / NT, NT>>>(x, Wl, bl, Wr, br, N);
    k_logits<<<(int)(((size_t)warpsL * 32 + NT - 1) / NT), NT>>>(ei, ea, We, att, E);
    k_alpha<<<(E / 2 + NT - 1) / NT, NT>>>(ei, alpha_out, E);
    k_node_hw<<<(N + NHB - 1) / NHB, 256>>>(gat_bias, gcn_W, N);
    k_gcn_edge<<<(int)(((size_t)warpsG * 32 + NT - 1) / NT), NT>>>(ei, E);
    k_node_out<<<(int)(((size_t)N * 32 + NT - 1) / NT), NT>>>(gcn_b, out_W, out_b, out, N);
}

// round 11
// speedup vs baseline: 1.2588x; 1.0201x over previous
#include <cuda_runtime.h>
#include <cuda_bf16.h>

// GNN_Attention: N=50000, E=800000, IN=8, ED=2, H=2, C=64, HID=64, OUT=2
#define MAXN 50000
#define MAXE 800000
#define HC   128
#define HID  64
#define NEG_SLOPE 0.2f

// -------- static device scratch (16B aligned for float4 / red.v4) --------
__device__ __align__(16) float g_xl[MAXN * HC];
__device__ __align__(16) float g_xr[MAXN * HC];
__device__ __align__(16) float g_expl[MAXE * 2];
__device__ __align__(16) float g_denom[MAXN * 2];
__device__ __align__(16) float g_hacc[MAXN * HC];   // Σ p·xl[src]  (unnormalized)
__device__ __align__(16) float g_hw[MAXN * HID];    // (h @ gcn_W.T) * 1{n has in-edges}
__device__ __align__(16) float g_h2acc[MAXN * HID];

__device__ __forceinline__ void red_add_v4(float* p, float4 v) {
    asm volatile("red.global.add.v4.f32 [%0], {%1,%2,%3,%4};"
                 :: "l"(p), "f"(v.x), "f"(v.y), "f"(v.z), "f"(v.w)
                 : "memory");
}
__device__ __forceinline__ void red_add_v2(float* p, float a, float b) {
    asm volatile("red.global.add.v2.f32 [%0], {%1,%2};"
                 :: "l"(p), "f"(a), "f"(b)
                 : "memory");
}

// -------- 1. node projections + zero all accumulators (fused) --------
__global__ void k_proj(const float* __restrict__ x,
                       const float* __restrict__ Wl, const float* __restrict__ bl,
                       const float* __restrict__ Wr, const float* __restrict__ br,
                       int N) {
    int idx = blockIdx.x * blockDim.x + threadIdx.x;
    if (idx >= N * HC) return;
    g_hacc[idx] = 0.f;
    if (idx < N * HID) g_h2acc[idx] = 0.f;
    if (idx < N * 2)   g_denom[idx] = 0.f;

    int n = idx >> 7, ch = idx & 127;
    const float* xv = x + n * 8;
    float sl = bl[ch], sr = br[ch];
    #pragma unroll
    for (int i = 0; i < 8; i++) {
        float xi = xv[i];
        sl += xi * Wl[ch * 8 + i];
        sr += xi * Wr[ch * 8 + i];
    }
    g_xl[idx] = sl;
    g_xr[idx] = sr;
}

// -------- 2. fused logits + exp + denom + unnormalized message scatter ------
__global__ void k_logits(const int* __restrict__ ei,
                         const float* __restrict__ ea,
                         const float* __restrict__ We,
                         const float* __restrict__ att, int E) {
    int warp = (blockIdx.x * blockDim.x + threadIdx.x) >> 5;
    int lane = threadIdx.x & 31;
    int e0 = warp * 4;
    if (e0 >= E) return;

    float4 at   = ((const float4*)att)[lane];
    float4 we01 = ((const float4*)We)[2 * lane];
    float4 we23 = ((const float4*)We)[2 * lane + 1];

    int src[4], dst[4];
    float2 eav[4];
    #pragma unroll
    for (int j = 0; j < 4; j++) {
        int e = min(e0 + j, E - 1);
        src[j] = ei[e];
        dst[j] = ei[E + e];
        eav[j] = ((const float2*)ea)[e];
    }
    float4 a[4], b[4];
    #pragma unroll
    for (int j = 0; j < 4; j++) a[j] = ((const float4*)g_xl)[src[j] * 32 + lane];
    #pragma unroll
    for (int j = 0; j < 4; j++) b[j] = ((const float4*)g_xr)[dst[j] * 32 + lane];

    float s[4];
    #pragma unroll
    for (int j = 0; j < 4; j++) {
        float e_0 = we01.x * eav[j].x + we01.y * eav[j].y;
        float e_1 = we01.z * eav[j].x + we01.w * eav[j].y;
        float e_2 = we23.x * eav[j].x + we23.y * eav[j].y;
        float e_3 = we23.z * eav[j].x + we23.w * eav[j].y;
        float z, acc = 0.f;
        z = a[j].x + b[j].x + e_0; z = z > 0.f ? z : NEG_SLOPE * z; acc += z * at.x;
        z = a[j].y + b[j].y + e_1; z = z > 0.f ? z : NEG_SLOPE * z; acc += z * at.y;
        z = a[j].z + b[j].z + e_2; z = z > 0.f ? z : NEG_SLOPE * z; acc += z * at.z;
        z = a[j].w + b[j].w + e_3; z = z > 0.f ? z : NEG_SLOPE * z; acc += z * at.w;
        s[j] = acc;
    }
    #pragma unroll
    for (int o = 8; o >= 1; o >>= 1) {
        #pragma unroll
        for (int j = 0; j < 4; j++)
            s[j] += __shfl_xor_sync(0xffffffffu, s[j], o, 16);
    }
    float p[4], pd[4];
    #pragma unroll
    for (int j = 0; j < 4; j++) p[j] = __expf(s[j]);  // |logit| small: no max-sub
    #pragma unroll
    for (int j = 0; j < 4; j++) pd[j] = __shfl_down_sync(0xffffffffu, p[j], 16);

    // epilogue distributed across lanes 0-3 (one edge each)
    if (lane < 4) {
        float myp  = (lane == 0) ? p[0]  : (lane == 1) ? p[1]  : (lane == 2) ? p[2]  : p[3];
        float mypd = (lane == 0) ? pd[0] : (lane == 1) ? pd[1] : (lane == 2) ? pd[2] : pd[3];
        int   myd  = (lane == 0) ? dst[0]: (lane == 1) ? dst[1]: (lane == 2) ? dst[2]: dst[3];
        int e = e0 + lane;
        if (e < E) {
            ((float2*)g_expl)[e] = make_float2(myp, mypd);
            red_add_v2(&g_denom[2 * myd], myp, mypd);
        }
    }
    #pragma unroll
    for (int j = 0; j < 4; j++) {
        if (e0 + j < E) {
            float4 m = a[j];
            m.x *= p[j]; m.y *= p[j]; m.z *= p[j]; m.w *= p[j];
            red_add_v4(&g_hacc[dst[j] * HC + lane * 4], m);
        }
    }
}

// -------- 3. register-tiled node GEMM: 64 nodes/block, 4x4 tile/thread ------
// g_hw = (relu(hacc/denom + bias) @ gcn_W.T) * 1{denom>0}
// (deg == 1 identically: softmax sums to 1 per head, so dinv is an indicator)
#define NHB 64
#define WP  68
__global__ void k_node_hw(const float* __restrict__ gat_bias,
                          const float* __restrict__ gcn_W, int N) {
    __shared__ __align__(16) float Wsh[64 * WP];   // 17.4 KB
    __shared__ __align__(16) float hsh[64 * WP];   // 17.4 KB
    __shared__ float inv0[NHB], inv1[NHB], dsh[NHB];
    __shared__ float bsh[HC];
    int t = threadIdx.x;                 // 256
    int base = blockIdx.x * NHB;

    if (t < HC) bsh[t] = gat_bias[t];
    if (t < NHB) {
        int n = base + t;
        if (n < N) {
            float2 dn = ((const float2*)g_denom)[n];
            inv0[t] = dn.x > 0.f ? __fdividef(1.f, dn.x) : 0.f;
            inv1[t] = dn.y > 0.f ? __fdividef(1.f, dn.y) : 0.f;
            dsh[t]  = dn.x > 0.f ? 1.f : 0.f;   // indicator(n has in-edges)
        } else { inv0[t] = 0.f; inv1[t] = 0.f; dsh[t] = 0.f; }
    }
    __syncthreads();

    int tx = t & 15;          // col group: cols 4tx..4tx+3
    int ty = t >> 4;          // node group: nodes 4ty..4ty+3
    float acc[4][4];
    #pragma unroll
    for (int i = 0; i < 4; i++)
        #pragma unroll
        for (int j = 0; j < 4; j++) acc[i][j] = 0.f;

    #pragma unroll
    for (int ph = 0; ph < 2; ph++) {
        {
            int k = t & 63, cb = t >> 6;
            #pragma unroll
            for (int j = 0; j < 16; j++) {
                int c = cb + j * 4;
                Wsh[k * WP + c] = gcn_W[c * HC + ph * 64 + k];
            }
        }
        {
            int c = t & 63, nb = t >> 6;
            #pragma unroll
            for (int j = 0; j < 16; j++) {
                int nl = nb + j * 4;
                int n = base + nl;
                float v = 0.f;
                if (n < N) {
                    float iv = ph ? inv1[nl] : inv0[nl];
                    v = fmaxf(g_hacc[n * HC + ph * 64 + c] * iv + bsh[ph * 64 + c], 0.f);
                }
                hsh[c * WP + nl] = v;
            }
        }
        __syncthreads();
        #pragma unroll 4
        for (int k = 0; k < 64; k++) {
            float4 w = *(const float4*)&Wsh[k * WP + tx * 4];
            float4 h = *(const float4*)&hsh[k * WP + ty * 4];
            acc[0][0] += h.x * w.x; acc[0][1] += h.x * w.y;
            acc[0][2] += h.x * w.z; acc[0][3] += h.x * w.w;
            acc[1][0] += h.y * w.x; acc[1][1] += h.y * w.y;
            acc[1][2] += h.y * w.z; acc[1][3] += h.y * w.w;
            acc[2][0] += h.z * w.x; acc[2][1] += h.z * w.y;
            acc[2][2] += h.z * w.z; acc[2][3] += h.z * w.w;
            acc[3][0] += h.w * w.x; acc[3][1] += h.w * w.y;
            acc[3][2] += h.w * w.z; acc[3][3] += h.w * w.w;
        }
        __syncthreads();
    }
    #pragma unroll
    for (int i = 0; i < 4; i++) {
        int nl = ty * 4 + i;
        int n = base + nl;
        if (n < N) {
            float di = dsh[nl];          // indicator fold (src-side GCN norm)
            float4 o = make_float4(acc[i][0] * di, acc[i][1] * di,
                                   acc[i][2] * di, acc[i][3] * di);
            ((float4*)g_hw)[n * 16 + tx] = o;
        }
    }
}

// -------- 4. fused alpha + GCN edge scatter (k_alpha deleted) --------
// alpha = expl/denom[dst]; ew = mean; h2acc[dst] += ew·hw[src]
// (dinv[dst] == 1 for every edge; dinv[src] indicator pre-folded into hw)
__global__ void k_gcn_edge(const int* __restrict__ ei,
                           float* __restrict__ alpha_out, int E) {
    int warp = (blockIdx.x * blockDim.x + threadIdx.x) >> 5;
    int lane = threadIdx.x & 31;
    int half = lane >> 4;
    int l    = lane & 15;
    int e0 = warp * 8 + half;
    if (e0 >= E) return;

    int src[4], dst[4];
    #pragma unroll
    for (int j = 0; j < 4; j++) {
        int e = min(e0 + 2 * j, E - 1);
        src[j] = ei[e];
        dst[j] = ei[E + e];
    }
    float2 pe[4];
    #pragma unroll
    for (int j = 0; j < 4; j++) pe[j] = ((const float2*)g_expl)[min(e0 + 2 * j, E - 1)];
    float2 dn[4];
    #pragma unroll
    for (int j = 0; j < 4; j++) dn[j] = ((const float2*)g_denom)[dst[j]];

    float nv[4];
    #pragma unroll
    for (int j = 0; j < 4; j++) {
        float a0 = __fdividef(pe[j].x, dn[j].x);
        float a1 = __fdividef(pe[j].y, dn[j].y);
        nv[j] = 0.5f * (a0 + a1);
        int e = e0 + 2 * j;
        if (l == 0 && e < E)
            ((float2*)alpha_out)[e] = make_float2(a0, a1);
    }
    float4 v[4];
    #pragma unroll
    for (int j = 0; j < 4; j++)
        v[j] = ((const float4*)g_hw)[src[j] * 16 + l];
    #pragma unroll
    for (int j = 0; j < 4; j++) {
        if (e0 + 2 * j < E) {
            float4 m = v[j];
            m.x *= nv[j]; m.y *= nv[j]; m.z *= nv[j]; m.w *= nv[j];
            red_add_v4(&g_h2acc[dst[j] * HID + l * 4], m);
        }
    }
}

// -------- 5. per-node output --------
__global__ void k_node_out(const float* __restrict__ gcn_b,
                           const float* __restrict__ out_W,
                           const float* __restrict__ out_b,
                           float* __restrict__ out, int N) {
    int t = blockIdx.x * blockDim.x + threadIdx.x;
    int n = t >> 5;
    if (n >= N) return;
    int lane = t & 31;
    float2 hv = ((const float2*)g_h2acc)[n * 32 + lane];
    float h0 = fmaxf(hv.x + gcn_b[2 * lane],     0.f);
    float h1 = fmaxf(hv.y + gcn_b[2 * lane + 1], 0.f);
    float s0 = h0 * out_W[2 * lane]      + h1 * out_W[2 * lane + 1];
    float s1 = h0 * out_W[64 + 2 * lane] + h1 * out_W[64 + 2 * lane + 1];
    #pragma unroll
    for (int o = 16; o >= 1; o >>= 1) {
        s0 += __shfl_down_sync(0xffffffffu, s0, o);
        s1 += __shfl_down_sync(0xffffffffu, s1, o);
    }
    if (lane == 0) {
        out[2 * n]     = s0 + out_b[0];
        out[2 * n + 1] = s1 + out_b[1];
    }
}

extern "C" void kernel_launch(void* const* d_in, const int* in_sizes, int n_in,
                              void* d_out, int out_size) {
    const float* x        = (const float*)d_in[0];
    const float* ea       = (const float*)d_in[1];
    const int*   ei       = (const int*)d_in[2];   // int32 (JAX x64 disabled)
    const float* Wl       = (const float*)d_in[3];
    const float* bl       = (const float*)d_in[4];
    const float* Wr       = (const float*)d_in[5];
    const float* br       = (const float*)d_in[6];
    const float* We       = (const float*)d_in[7];
    const float* att      = (const float*)d_in[8];
    const float* gat_bias = (const float*)d_in[9];
    const float* gcn_W    = (const float*)d_in[10];
    const float* gcn_b    = (const float*)d_in[11];
    const float* out_W    = (const float*)d_in[12];
    const float* out_b    = (const float*)d_in[13];

    int N = in_sizes[0] / 8;     // IN=8
    int E = in_sizes[1] / 2;     // ED=2

    float* out       = (float*)d_out;
    float* alpha_out = (float*)d_out + (size_t)N * 2;

    const int NT = 256;
    int warpsL = (E + 3) / 4;   // 4 edges/warp
    int warpsG = (E + 7) / 8;   // 8 edges/warp
    k_proj<<<(N * HC + NT - 1) / NT, NT>>>(x, Wl, bl, Wr, br, N);
    k_logits<<<(int)(((size_t)warpsL * 32 + NT - 1) / NT), NT>>>(ei, ea, We, att, E);
    k_node_hw<<<(N + NHB - 1) / NHB, 256>>>(gat_bias, gcn_W, N);
    k_gcn_edge<<<(int)(((size_t)warpsG * 32 + NT - 1) / NT), NT>>>(ei, alpha_out, E);
    k_node_out<<<(int)(((size_t)N * 32 + NT - 1) / NT), NT>>>(gcn_b, out_W, out_b, out, N);
}